// round 3
// baseline (speedup 1.0000x reference)
#include <cuda_runtime.h>

#define NN 50000
#define EE 1600000
#define RR 7
#define DD 128
#define GG 64
#define NRSEG (NN * RR)          // 350000 segments
#define SCAN_B 1024
#define NB1 ((NRSEG + SCAN_B - 1) / SCAN_B)   // 342

// ---------------- static device scratch (no allocations allowed) ------------
__device__ float g_x[2][NN * DD];                 // ping-pong activations (25.6MB x2)
__device__ float g_upd[(size_t)NRSEG * DD];       // segment sums [N*R][D] (179.2MB)
__device__ int   g_counts[NRSEG];
__device__ int   g_offs[NRSEG + 1];
__device__ int   g_cursor[NRSEG];
__device__ int   g_bsums[SCAN_B];
__device__ int   g_srcs[EE];                      // node_in, segment-sorted
__device__ float g_ws[EE];                        // edge_weight, segment-sorted

// ---------------- init: x0 = emb[unit_type] ---------------------------------
__global__ void k_init_x(const int* __restrict__ unit_type,
                         const float* __restrict__ emb) {
    int i = blockIdx.x * blockDim.x + threadIdx.x;
    if (i >= NN * DD) return;
    int n = i >> 7, d = i & 127;
    g_x[0][i] = emb[unit_type[n] * DD + d];
}

__global__ void k_zero_out(float* __restrict__ out) {
    int i = blockIdx.x * blockDim.x + threadIdx.x;
    if (i < GG * DD) out[i] = 0.0f;
}

// ---------------- CSR build --------------------------------------------------
__global__ void k_zero_counts() {
    int i = blockIdx.x * blockDim.x + threadIdx.x;
    if (i < NRSEG) g_counts[i] = 0;
}

__global__ void k_hist(const int* __restrict__ node_out,
                       const int* __restrict__ rel) {
    int i = blockIdx.x * blockDim.x + threadIdx.x;
    if (i < EE) atomicAdd(&g_counts[node_out[i] * RR + rel[i]], 1);
}

__device__ __forceinline__ void scan_body(const int* in, int* out, int* bsums, int n) {
    __shared__ int s[SCAN_B];
    int i = blockIdx.x * SCAN_B + threadIdx.x;
    int v = (i < n) ? in[i] : 0;
    s[threadIdx.x] = v;
    __syncthreads();
    #pragma unroll
    for (int off = 1; off < SCAN_B; off <<= 1) {
        int t = (threadIdx.x >= off) ? s[threadIdx.x - off] : 0;
        __syncthreads();
        s[threadIdx.x] += t;
        __syncthreads();
    }
    if (i < n) out[i] = s[threadIdx.x] - v;          // exclusive
    if (bsums && threadIdx.x == SCAN_B - 1) bsums[blockIdx.x] = s[SCAN_B - 1];
}

__global__ void k_scan1() { scan_body(g_counts, g_offs, g_bsums, NRSEG); }
__global__ void k_scan2() { scan_body(g_bsums, g_bsums, nullptr, NB1); }

__global__ void k_scan_add() {
    int i = blockIdx.x * blockDim.x + threadIdx.x;
    if (i < NRSEG) {
        int o = g_offs[i] + g_bsums[i >> 10];
        g_offs[i]   = o;
        g_cursor[i] = o;
    }
    if (i == 0) g_offs[NRSEG] = EE;
}

__global__ void k_fill(const int* __restrict__ node_in,
                       const int* __restrict__ node_out,
                       const int* __restrict__ rel,
                       const float* __restrict__ ew) {
    int i = blockIdx.x * blockDim.x + threadIdx.x;
    if (i >= EE) return;
    int seg = node_out[i] * RR + rel[i];
    int p = atomicAdd(&g_cursor[seg], 1);
    g_srcs[p] = node_in[i];
    g_ws[p]   = ew[i];
}

// ---------------- per-layer edge scatter: one warp per segment ---------------
__global__ void k_scatter(int layer) {
    int gw   = (blockIdx.x * blockDim.x + threadIdx.x) >> 5;
    int lane = threadIdx.x & 31;
    if (gw >= NRSEG) return;
    const float4* __restrict__ xv = (const float4*)g_x[layer & 1];
    int beg = g_offs[gw], end = g_offs[gw + 1];
    float4 acc = make_float4(0.f, 0.f, 0.f, 0.f);
    for (int e = beg; e < end; ++e) {
        int   s = g_srcs[e];          // broadcast
        float w = g_ws[e];            // broadcast
        float4 v = xv[(size_t)s * 32 + lane];
        acc.x += v.x * w; acc.y += v.y * w;
        acc.z += v.z * w; acc.w += v.w * w;
    }
    ((float4*)g_upd)[(size_t)gw * 32 + lane] = acc;
}

// ---------------- fused GEMM: h = [upd|x] @ [Wrel;Wloop] + b, relu -----------
// M=50000, K=1024 (896 from upd + 128 from x), N=128. BM=BN=128, BK=16,
// 256 threads, 8x8 microtile per thread.
__global__ void __launch_bounds__(256, 2)
k_gemm(const float* __restrict__ Wrel,   // [896][128] for this layer
       const float* __restrict__ Wloop,  // [128][128]
       const float* __restrict__ brel,   // [128]
       const float* __restrict__ bloop,  // [128]
       int layer, float* __restrict__ out_ext) {
    __shared__ float As[16][128];        // transposed A tile: As[k][m]
    __shared__ float Bs[16][128];        // Bs[k][n]

    const float* __restrict__ xin = g_x[layer & 1];
    float* __restrict__ xout = out_ext ? out_ext : g_x[(layer + 1) & 1];

    int tid  = threadIdx.x;
    int row0 = blockIdx.x * 128;
    int tx = tid & 15, ty = tid >> 4;

    float acc[8][8];
    #pragma unroll
    for (int i = 0; i < 8; i++)
        #pragma unroll
        for (int j = 0; j < 8; j++) acc[i][j] = 0.f;

    int aRow = tid >> 1;                 // 0..127
    int aCol = (tid & 1) * 8;            // 0 or 8
    int bRow = tid >> 4;                 // 0..15
    int bCol = (tid & 15) * 8;           // 0..120
    int gm   = row0 + aRow;

    for (int kt = 0; kt < 64; ++kt) {    // tiles 0..55: upd/Wrel, 56..63: x/Wloop
        int k0 = kt << 4;
        float4 a0, a1;
        if (gm < NN) {
            const float* ap = (k0 < 896)
                ? (g_upd + (size_t)gm * 896 + k0 + aCol)
                : (xin   + (size_t)gm * 128 + (k0 - 896) + aCol);
            a0 = ((const float4*)ap)[0];
            a1 = ((const float4*)ap)[1];
        } else {
            a0 = make_float4(0.f, 0.f, 0.f, 0.f);
            a1 = a0;
        }
        int gk = k0 + bRow;
        const float* bp = (gk < 896) ? (Wrel + (size_t)gk * 128 + bCol)
                                     : (Wloop + (size_t)(gk - 896) * 128 + bCol);
        float4 b0 = ((const float4*)bp)[0];
        float4 b1 = ((const float4*)bp)[1];

        As[aCol + 0][aRow] = a0.x; As[aCol + 1][aRow] = a0.y;
        As[aCol + 2][aRow] = a0.z; As[aCol + 3][aRow] = a0.w;
        As[aCol + 4][aRow] = a1.x; As[aCol + 5][aRow] = a1.y;
        As[aCol + 6][aRow] = a1.z; As[aCol + 7][aRow] = a1.w;
        *(float4*)&Bs[bRow][bCol]     = b0;
        *(float4*)&Bs[bRow][bCol + 4] = b1;
        __syncthreads();

        #pragma unroll
        for (int k = 0; k < 16; ++k) {
            float ra[8], rb[8];
            *(float4*)(ra)     = *(const float4*)&As[k][ty * 8];
            *(float4*)(ra + 4) = *(const float4*)&As[k][ty * 8 + 4];
            *(float4*)(rb)     = *(const float4*)&Bs[k][tx * 8];
            *(float4*)(rb + 4) = *(const float4*)&Bs[k][tx * 8 + 4];
            #pragma unroll
            for (int i = 0; i < 8; i++)
                #pragma unroll
                for (int j = 0; j < 8; j++)
                    acc[i][j] += ra[i] * rb[j];
        }
        __syncthreads();
    }

    #pragma unroll
    for (int i = 0; i < 8; i++) {
        int m = row0 + ty * 8 + i;
        if (m >= NN) continue;
        #pragma unroll
        for (int j = 0; j < 8; j += 4) {
            int n = tx * 8 + j;
            float4 v;
            v.x = fmaxf(acc[i][j + 0] + brel[n + 0] + bloop[n + 0], 0.f);
            v.y = fmaxf(acc[i][j + 1] + brel[n + 1] + bloop[n + 1], 0.f);
            v.z = fmaxf(acc[i][j + 2] + brel[n + 2] + bloop[n + 2], 0.f);
            v.w = fmaxf(acc[i][j + 3] + brel[n + 3] + bloop[n + 3], 0.f);
            *(float4*)(xout + (size_t)m * 128 + n) = v;
        }
    }
}

// ---------------- graph pooling (node2graph is sorted) -----------------------
__global__ void k_segsum(const float* __restrict__ x,
                         const int* __restrict__ n2g,
                         float* __restrict__ out) {
    int d  = threadIdx.x;                // 128 threads, one column each
    int r0 = blockIdx.x * 512;
    if (r0 >= NN) return;
    int r1 = min(r0 + 512, NN);
    float acc = 0.f;
    int gcur = n2g[r0];
    for (int r = r0; r < r1; ++r) {
        int g = n2g[r];                  // broadcast load
        if (g != gcur) {
            atomicAdd(&out[gcur * DD + d], acc);
            acc = 0.f; gcur = g;
        }
        acc += x[(size_t)r * DD + d];
    }
    atomicAdd(&out[gcur * DD + d], acc);
}

// ---------------- launch -----------------------------------------------------
extern "C" void kernel_launch(void* const* d_in, const int* in_sizes, int n_in,
                              void* d_out, int out_size) {
    const int*   unit_type   = (const int*)  d_in[0];
    const int*   node_in     = (const int*)  d_in[1];
    const int*   node_out    = (const int*)  d_in[2];
    const int*   relation    = (const int*)  d_in[3];
    const float* edge_weight = (const float*)d_in[4];
    const int*   node2graph  = (const int*)  d_in[5];
    const float* emb         = (const float*)d_in[6];
    const float* W_rel       = (const float*)d_in[7];   // [3][896][128]
    const float* b_rel       = (const float*)d_in[8];   // [3][128]
    const float* W_loop      = (const float*)d_in[9];   // [3][128][128]
    const float* b_loop      = (const float*)d_in[10];  // [3][128]

    float* out    = (float*)d_out;
    float* out_gf = out;              // [G][D]
    float* out_x  = out + GG * DD;    // [N][D]

    k_init_x<<<(NN * DD + 255) / 256, 256>>>(unit_type, emb);
    k_zero_out<<<(GG * DD + 255) / 256, 256>>>(out_gf);

    // CSR build (once; reused by all 3 layers)
    k_zero_counts<<<(NRSEG + 255) / 256, 256>>>();
    k_hist<<<(EE + 255) / 256, 256>>>(node_out, relation);
    k_scan1<<<NB1, SCAN_B>>>();
    k_scan2<<<1, SCAN_B>>>();
    k_scan_add<<<(NRSEG + 255) / 256, 256>>>();
    k_fill<<<(EE + 255) / 256, 256>>>(node_in, node_out, relation, edge_weight);

    for (int L = 0; L < 3; ++L) {
        k_scatter<<<(NRSEG * 32 + 255) / 256, 256>>>(L);
        float* oext = (L == 2) ? out_x : nullptr;
        k_gemm<<<(NN + 127) / 128, 256>>>(W_rel + (size_t)L * 896 * 128,
                                          W_loop + (size_t)L * 128 * 128,
                                          b_rel + L * 128, b_loop + L * 128,
                                          L, oext);
    }

    k_segsum<<<(NN + 511) / 512, 128>>>(out_x, node2graph, out_gf);
}

// round 6
// speedup vs baseline: 1.9213x; 1.9213x over previous
#include <cuda_runtime.h>
#include <cuda_bf16.h>

#define NN 50000
#define NPAD 50048
#define EE 1600000
#define RR 7
#define DD 128
#define GG 64
#define NRSEG (NN * RR)          // 350000
#define SCAN_B 1024
#define NB1 ((NRSEG + SCAN_B - 1) / SCAN_B)

// ---------------- static device scratch ------------------------------------
__device__ float g_x[2][(size_t)NPAD * DD];
__device__ __nv_bfloat16 g_xh[(size_t)NPAD * DD];
__device__ __nv_bfloat16 g_xl[(size_t)NPAD * DD];
__device__ __nv_bfloat16 g_uh[(size_t)NPAD * 896];
__device__ __nv_bfloat16 g_ul[(size_t)NPAD * 896];
__device__ __nv_bfloat16 g_Wh[3 * 128 * 1024];   // [L][n][k] transposed, k-contig
__device__ __nv_bfloat16 g_Wl[3 * 128 * 1024];
__device__ float g_bias[3 * 128];
__device__ int   g_counts[NRSEG];
__device__ int   g_offs[NRSEG + 1];
__device__ int   g_cursor[NRSEG];
__device__ int   g_bsums[SCAN_B];
__device__ int   g_srcs[EE];
__device__ float g_ws[EE];

// ---------------- helpers ----------------------------------------------------
__device__ __forceinline__ unsigned s2u(const void* p) {
    unsigned a;
    asm("{ .reg .u64 t; cvta.to.shared.u64 t, %1; cvt.u32.u64 %0, t; }" : "=r"(a) : "l"(p));
    return a;
}
__device__ __forceinline__ void cp16(unsigned dst, const void* src) {
    asm volatile("cp.async.cg.shared.global [%0], [%1], 16;" :: "r"(dst), "l"(src) : "memory");
}
__device__ __forceinline__ void cp_commit() { asm volatile("cp.async.commit_group;" ::: "memory"); }
__device__ __forceinline__ void cp_wait1()  { asm volatile("cp.async.wait_group 1;" ::: "memory"); }
__device__ __forceinline__ void cp_wait0()  { asm volatile("cp.async.wait_group 0;" ::: "memory"); }

__device__ __forceinline__ void mma16816(float* c, const unsigned* a, const unsigned* b) {
    asm volatile(
        "mma.sync.aligned.m16n8k16.row.col.f32.bf16.bf16.f32 "
        "{%0,%1,%2,%3}, {%4,%5,%6,%7}, {%8,%9}, {%0,%1,%2,%3};"
        : "+f"(c[0]), "+f"(c[1]), "+f"(c[2]), "+f"(c[3])
        : "r"(a[0]), "r"(a[1]), "r"(a[2]), "r"(a[3]), "r"(b[0]), "r"(b[1]));
}

// ---------------- init: x0 = emb[unit_type] + bf16 split ---------------------
__global__ void k_init_x(const int* __restrict__ unit_type,
                         const float* __restrict__ emb) {
    int i = blockIdx.x * blockDim.x + threadIdx.x;
    if (i >= NN * DD) return;
    int n = i >> 7, d = i & 127;
    float v = emb[unit_type[n] * DD + d];
    g_x[0][i] = v;
    __nv_bfloat16 h = __float2bfloat16(v);
    g_xh[i] = h;
    g_xl[i] = __float2bfloat16(v - __bfloat162float(h));
}

__global__ void k_zero_out(float* __restrict__ out) {
    int i = blockIdx.x * blockDim.x + threadIdx.x;
    if (i < GG * DD) out[i] = 0.0f;
}

// ---------------- weight transpose + bf16 split ------------------------------
__global__ void k_wconv(const float* __restrict__ Wrel,
                        const float* __restrict__ Wloop,
                        const float* __restrict__ brel,
                        const float* __restrict__ bloop) {
    int idx = blockIdx.x * blockDim.x + threadIdx.x;
    if (idx < 3 * 128 * 1024) {
        int L = idx >> 17;
        int r = idx & 131071;
        int n = r >> 10;
        int k = r & 1023;
        float w = (k < 896) ? Wrel[((size_t)L * 896 + k) * 128 + n]
                            : Wloop[((size_t)L * 128 + (k - 896)) * 128 + n];
        __nv_bfloat16 h = __float2bfloat16(w);
        g_Wh[idx] = h;
        g_Wl[idx] = __float2bfloat16(w - __bfloat162float(h));
    }
    if (idx < 3 * 128) g_bias[idx] = brel[idx] + bloop[idx];
}

// ---------------- CSR build --------------------------------------------------
__global__ void k_zero_counts() {
    int i = blockIdx.x * blockDim.x + threadIdx.x;
    if (i < NRSEG) g_counts[i] = 0;
}

__global__ void k_hist(const int* __restrict__ node_out,
                       const int* __restrict__ rel) {
    int i = blockIdx.x * blockDim.x + threadIdx.x;
    if (i < EE) atomicAdd(&g_counts[node_out[i] * RR + rel[i]], 1);
}

__device__ __forceinline__ void scan_body(const int* in, int* out, int* bsums, int n) {
    __shared__ int s[SCAN_B];
    int i = blockIdx.x * SCAN_B + threadIdx.x;
    int v = (i < n) ? in[i] : 0;
    s[threadIdx.x] = v;
    __syncthreads();
    #pragma unroll
    for (int off = 1; off < SCAN_B; off <<= 1) {
        int t = (threadIdx.x >= off) ? s[threadIdx.x - off] : 0;
        __syncthreads();
        s[threadIdx.x] += t;
        __syncthreads();
    }
    if (i < n) out[i] = s[threadIdx.x] - v;
    if (bsums && threadIdx.x == SCAN_B - 1) bsums[blockIdx.x] = s[SCAN_B - 1];
}

__global__ void k_scan1() { scan_body(g_counts, g_offs, g_bsums, NRSEG); }
__global__ void k_scan2() { scan_body(g_bsums, g_bsums, nullptr, NB1); }

__global__ void k_scan_add() {
    int i = blockIdx.x * blockDim.x + threadIdx.x;
    if (i < NRSEG) {
        int o = g_offs[i] + g_bsums[i >> 10];
        g_offs[i]   = o;
        g_cursor[i] = o;
    }
    if (i == 0) g_offs[NRSEG] = EE;
}

__global__ void k_fill(const int* __restrict__ node_in,
                       const int* __restrict__ node_out,
                       const int* __restrict__ rel,
                       const float* __restrict__ ew) {
    int i = blockIdx.x * blockDim.x + threadIdx.x;
    if (i >= EE) return;
    int seg = node_out[i] * RR + rel[i];
    int p = atomicAdd(&g_cursor[seg], 1);
    g_srcs[p] = node_in[i];
    g_ws[p]   = ew[i];
}

// ---------------- per-layer edge scatter -> bf16 hi/lo -----------------------
__global__ void k_scatter(int layer) {
    int gw   = (blockIdx.x * blockDim.x + threadIdx.x) >> 5;
    int lane = threadIdx.x & 31;
    if (gw >= NRSEG) return;
    const float4* __restrict__ xv = (const float4*)g_x[layer & 1];
    int beg = g_offs[gw], end = g_offs[gw + 1];
    float4 acc = make_float4(0.f, 0.f, 0.f, 0.f);
    for (int e = beg; e < end; ++e) {
        int   s = g_srcs[e];
        float w = g_ws[e];
        float4 v = xv[(size_t)s * 32 + lane];
        acc.x += v.x * w; acc.y += v.y * w;
        acc.z += v.z * w; acc.w += v.w * w;
    }
    size_t o = (size_t)gw * 128 + lane * 4;
    __nv_bfloat16 h0 = __float2bfloat16(acc.x);
    __nv_bfloat16 h1 = __float2bfloat16(acc.y);
    __nv_bfloat16 h2 = __float2bfloat16(acc.z);
    __nv_bfloat16 h3 = __float2bfloat16(acc.w);
    __nv_bfloat162 a, b; a.x = h0; a.y = h1; b.x = h2; b.y = h3;
    uint2 uh; uh.x = *(unsigned*)&a; uh.y = *(unsigned*)&b;
    __nv_bfloat162 c, d;
    c.x = __float2bfloat16(acc.x - __bfloat162float(h0));
    c.y = __float2bfloat16(acc.y - __bfloat162float(h1));
    d.x = __float2bfloat16(acc.z - __bfloat162float(h2));
    d.y = __float2bfloat16(acc.w - __bfloat162float(h3));
    uint2 ul; ul.x = *(unsigned*)&c; ul.y = *(unsigned*)&d;
    *(uint2*)(g_uh + o) = uh;
    *(uint2*)(g_ul + o) = ul;
}

// ---------------- mma.sync GEMM: h = [upd|x] @ W + b, relu -------------------
// CTA: 128 rows x 128 cols, K=1024 (896 upd + 128 x), BK=64, double-buffered
// cp.async. 3-term bf16 split into fp32 accum: Ah*Bh + Ah*Bl + Al*Bh.
// Smem tiles [row][72 bf16] (144B stride) -> conflict-free 32b fragment loads.
#define TSTRIDE 72
#define TBYTES  (128 * TSTRIDE * 2)          // 18432 per tile
#define STAGEB  (4 * TBYTES)                 // Ah,Al,Bh,Bl = 73728
#define SMTOT   (2 * STAGEB)                 // 147456

__device__ __forceinline__ void load_chunk(char* sm, int stage, int c,
                                           int row0, int layer, int tid) {
    unsigned base = s2u(sm) + (unsigned)stage * STAGEB;
    const __nv_bfloat16* wh = g_Wh + (size_t)layer * 131072;
    const __nv_bfloat16* wl = g_Wl + (size_t)layer * 131072;
    #pragma unroll
    for (int i = 0; i < 16; i++) {
        int idx = tid + 256 * i;             // 4096 x 16B units
        int arr = idx >> 10;
        int rem = idx & 1023;
        int row = rem >> 3;
        int seg = rem & 7;
        unsigned dst = base + (unsigned)arr * TBYTES + row * 144u + seg * 16u;
        const __nv_bfloat16* src;
        if (arr < 2) {                        // A (hi / lo)
            if (c < 14) {
                size_t o = (size_t)(row0 + row) * 896 + c * 64 + seg * 8;
                src = (arr == 0 ? g_uh : g_ul) + o;
            } else {
                size_t o = (size_t)(row0 + row) * 128 + (c - 14) * 64 + seg * 8;
                src = (arr == 0 ? g_xh : g_xl) + o;
            }
        } else {                              // B (hi / lo)
            size_t o = (size_t)row * 1024 + c * 64 + seg * 8;
            src = (arr == 2 ? wh : wl) + o;
        }
        cp16(dst, src);
    }
}

__global__ void __launch_bounds__(256, 1)
k_gemm(int layer, float* __restrict__ xout_ext, int dosplit) {
    extern __shared__ char sm[];
    __shared__ float s_bias[128];

    int tid  = threadIdx.x;
    int wid  = tid >> 5, lane = tid & 31;
    int wm   = wid & 1;                      // 2 warps in m
    int wn   = wid >> 1;                     // 4 warps in n
    int row0 = blockIdx.x * 128;
    float* __restrict__ xout = xout_ext ? xout_ext : g_x[(layer + 1) & 1];

    if (tid < 128) s_bias[tid] = g_bias[layer * 128 + tid];

    float acc[4][4][4];
    #pragma unroll
    for (int a = 0; a < 4; a++)
        #pragma unroll
        for (int b = 0; b < 4; b++)
            #pragma unroll
            for (int e = 0; e < 4; e++) acc[a][b][e] = 0.f;

    load_chunk(sm, 0, 0, row0, layer, tid);
    cp_commit();

    const int g = lane >> 2, q = lane & 3;
    for (int c = 0; c < 16; ++c) {
        if (c < 15) {
            load_chunk(sm, (c + 1) & 1, c + 1, row0, layer, tid);
            cp_commit();
            cp_wait1();
        } else {
            cp_wait0();
        }
        __syncthreads();

        const char* st = sm + (c & 1) * STAGEB;
        const char* Ah = st;
        const char* Al = st + TBYTES;
        const char* Bh = st + 2 * TBYTES;
        const char* Bl = st + 3 * TBYTES;

        #pragma unroll
        for (int ks = 0; ks < 4; ++ks) {
            int k0 = ks * 16 + 2 * q;        // bf16 element index in row
            unsigned ah[4][4], al_[4][4], bh[4][2], bl[4][2];
            #pragma unroll
            for (int mt = 0; mt < 4; ++mt) {
                int r = wm * 64 + mt * 16 + g;
                ah[mt][0] = *(const unsigned*)(Ah + r * 144 + k0 * 2);
                ah[mt][1] = *(const unsigned*)(Ah + (r + 8) * 144 + k0 * 2);
                ah[mt][2] = *(const unsigned*)(Ah + r * 144 + (k0 + 8) * 2);
                ah[mt][3] = *(const unsigned*)(Ah + (r + 8) * 144 + (k0 + 8) * 2);
                al_[mt][0] = *(const unsigned*)(Al + r * 144 + k0 * 2);
                al_[mt][1] = *(const unsigned*)(Al + (r + 8) * 144 + k0 * 2);
                al_[mt][2] = *(const unsigned*)(Al + r * 144 + (k0 + 8) * 2);
                al_[mt][3] = *(const unsigned*)(Al + (r + 8) * 144 + (k0 + 8) * 2);
            }
            #pragma unroll
            for (int nt = 0; nt < 4; ++nt) {
                int n = wn * 32 + nt * 8 + g;
                bh[nt][0] = *(const unsigned*)(Bh + n * 144 + k0 * 2);
                bh[nt][1] = *(const unsigned*)(Bh + n * 144 + (k0 + 8) * 2);
                bl[nt][0] = *(const unsigned*)(Bl + n * 144 + k0 * 2);
                bl[nt][1] = *(const unsigned*)(Bl + n * 144 + (k0 + 8) * 2);
            }
            #pragma unroll
            for (int mt = 0; mt < 4; ++mt)
                #pragma unroll
                for (int nt = 0; nt < 4; ++nt) {
                    mma16816(acc[mt][nt], ah[mt],  bh[nt]);
                    mma16816(acc[mt][nt], ah[mt],  bl[nt]);
                    mma16816(acc[mt][nt], al_[mt], bh[nt]);
                }
        }
        __syncthreads();
    }

    // epilogue: bias + relu, fp32 store (+ bf16 split for next layer)
    #pragma unroll
    for (int mt = 0; mt < 4; ++mt) {
        int m0 = row0 + wm * 64 + mt * 16 + g;
        #pragma unroll
        for (int nt = 0; nt < 4; ++nt) {
            int col = wn * 32 + nt * 8 + 2 * q;
            float b0 = s_bias[col], b1 = s_bias[col + 1];
            #pragma unroll
            for (int half = 0; half < 2; ++half) {
                int m = m0 + half * 8;
                if (m >= NN) continue;
                float v0 = fmaxf(acc[mt][nt][2 * half]     + b0, 0.f);
                float v1 = fmaxf(acc[mt][nt][2 * half + 1] + b1, 0.f);
                float2* dst = (float2*)(xout + (size_t)m * 128 + col);
                *dst = make_float2(v0, v1);
                if (dosplit) {
                    __nv_bfloat16 h0 = __float2bfloat16(v0);
                    __nv_bfloat16 h1 = __float2bfloat16(v1);
                    __nv_bfloat162 hh; hh.x = h0; hh.y = h1;
                    *(unsigned*)(g_xh + (size_t)m * 128 + col) = *(unsigned*)&hh;
                    __nv_bfloat162 ll;
                    ll.x = __float2bfloat16(v0 - __bfloat162float(h0));
                    ll.y = __float2bfloat16(v1 - __bfloat162float(h1));
                    *(unsigned*)(g_xl + (size_t)m * 128 + col) = *(unsigned*)&ll;
                }
            }
        }
    }
}

// ---------------- graph pooling (node2graph sorted) --------------------------
__global__ void k_segsum(const float* __restrict__ x,
                         const int* __restrict__ n2g,
                         float* __restrict__ out) {
    int d  = threadIdx.x;
    int r0 = blockIdx.x * 512;
    if (r0 >= NN) return;
    int r1 = min(r0 + 512, NN);
    float acc = 0.f;
    int gcur = n2g[r0];
    for (int r = r0; r < r1; ++r) {
        int g = n2g[r];
        if (g != gcur) {
            atomicAdd(&out[gcur * DD + d], acc);
            acc = 0.f; gcur = g;
        }
        acc += x[(size_t)r * DD + d];
    }
    atomicAdd(&out[gcur * DD + d], acc);
}

// ---------------- launch -----------------------------------------------------
extern "C" void kernel_launch(void* const* d_in, const int* in_sizes, int n_in,
                              void* d_out, int out_size) {
    const int*   unit_type   = (const int*)  d_in[0];
    const int*   node_in     = (const int*)  d_in[1];
    const int*   node_out    = (const int*)  d_in[2];
    const int*   relation    = (const int*)  d_in[3];
    const float* edge_weight = (const float*)d_in[4];
    const int*   node2graph  = (const int*)  d_in[5];
    const float* emb         = (const float*)d_in[6];
    const float* W_rel       = (const float*)d_in[7];
    const float* b_rel       = (const float*)d_in[8];
    const float* W_loop      = (const float*)d_in[9];
    const float* b_loop      = (const float*)d_in[10];

    float* out    = (float*)d_out;
    float* out_gf = out;
    float* out_x  = out + GG * DD;

    cudaFuncSetAttribute(k_gemm, cudaFuncAttributeMaxDynamicSharedMemorySize, SMTOT);

    k_init_x<<<(NN * DD + 255) / 256, 256>>>(unit_type, emb);
    k_zero_out<<<(GG * DD + 255) / 256, 256>>>(out_gf);
    k_wconv<<<(3 * 128 * 1024 + 255) / 256, 256>>>(W_rel, W_loop, b_rel, b_loop);

    k_zero_counts<<<(NRSEG + 255) / 256, 256>>>();
    k_hist<<<(EE + 255) / 256, 256>>>(node_out, relation);
    k_scan1<<<NB1, SCAN_B>>>();
    k_scan2<<<1, SCAN_B>>>();
    k_scan_add<<<(NRSEG + 255) / 256, 256>>>();
    k_fill<<<(EE + 255) / 256, 256>>>(node_in, node_out, relation, edge_weight);

    for (int L = 0; L < 3; ++L) {
        k_scatter<<<(NRSEG * 32 + 255) / 256, 256>>>(L);
        float* oext = (L == 2) ? out_x : nullptr;
        k_gemm<<<(NN + 127) / 128, 256, SMTOT>>>(L, oext, (L < 2) ? 1 : 0);
    }

    k_segsum<<<(NN + 511) / 512, 128>>>(out_x, node2graph, out_gf);
}